// round 7
// baseline (speedup 1.0000x reference)
#include <cuda_runtime.h>
#include <cuda_fp16.h>
#include <math.h>
#include <stdint.h>

#define NTOK 4096
#define DDIM 512
#define IDIM 2048
#define NEXP 8
#define MAXTILES 40
#define SA 40                 // smem row stride in halves (80 B)
#define STG 20480             // stage bytes: A 128*80 + B 128*80
#define SMEMSZ (3 * STG)      // 61440

// ===================== device scratch =====================
__device__ int g_expert[NTOK];
__device__ int g_pos[NTOK];
__device__ int g_perm[NTOK];
__device__ int g_cnt[NEXP];
__device__ int g_off[NEXP];
__device__ int g_tileE[64];
__device__ int g_tileRow[64];
__device__ int g_tileCnt[64];
__device__ int g_numTiles;

__device__ float g_A1[(size_t)NTOK * IDIM];
__device__ __half g_Hsh[(size_t)NTOK * IDIM];
__device__ __half g_Hrh[(size_t)NTOK * IDIM];

__device__ __half g_xh[(size_t)NTOK * DDIM];
__device__ __half g_sw1h[(size_t)IDIM * DDIM];
__device__ __half g_sw2h[(size_t)DDIM * IDIM];
__device__ __half g_w1h[(size_t)NEXP * IDIM * DDIM];
__device__ __half g_w3h[(size_t)NEXP * IDIM * DDIM];
__device__ __half g_w2h[(size_t)NEXP * DDIM * IDIM];

// ===================== PTX helpers =====================
__device__ __forceinline__ uint32_t smem_u32(const void* p) {
    uint32_t a;
    asm("{ .reg .u64 t; cvta.to.shared.u64 t, %1; cvt.u32.u64 %0, t; }" : "=r"(a) : "l"(p));
    return a;
}
#define CP16(dst, src) asm volatile("cp.async.cg.shared.global [%0], [%1], 16;" :: "r"(dst), "l"(src))
#define CP_COMMIT()    asm volatile("cp.async.commit_group;" ::: "memory")
#define CP_WAIT2()     asm volatile("cp.async.wait_group 2;" ::: "memory")

#define LDSM4(r0, r1, r2, r3, a) \
    asm volatile("ldmatrix.sync.aligned.m8n8.x4.shared.b16 {%0,%1,%2,%3}, [%4];" \
        : "=r"(r0), "=r"(r1), "=r"(r2), "=r"(r3) : "r"(a))

#define MMAH(d, A, B) \
    asm volatile("mma.sync.aligned.m16n8k16.row.col.f32.f16.f16.f32 " \
        "{%0,%1,%2,%3},{%4,%5,%6,%7},{%8,%9},{%0,%1,%2,%3};" \
        : "+f"((d)[0]), "+f"((d)[1]), "+f"((d)[2]), "+f"((d)[3]) \
        : "r"((A)[0]), "r"((A)[1]), "r"((A)[2]), "r"((A)[3]), "r"((B)[0]), "r"((B)[1]))

// ===================== setup kernels =====================
__global__ void zero_kernel() {
    if (threadIdx.x < NEXP) g_cnt[threadIdx.x] = 0;
}

__global__ void gate_kernel(const float* __restrict__ x, const float* __restrict__ gw) {
    int warp = (int)((blockIdx.x * blockDim.x + threadIdx.x) >> 5);
    int lane = threadIdx.x & 31;
    if (warp >= NTOK) return;
    const float4* xr = reinterpret_cast<const float4*>(x + (size_t)warp * DDIM + lane * 16);
    float4 xv[4];
#pragma unroll
    for (int j = 0; j < 4; j++) xv[j] = xr[j];
    float best = -1e30f; int bi = 0;
#pragma unroll
    for (int e = 0; e < NEXP; e++) {
        const float4* gr = reinterpret_cast<const float4*>(gw + (size_t)e * DDIM + lane * 16);
        float s = 0.f;
#pragma unroll
        for (int j = 0; j < 4; j++) {
            float4 g = gr[j];
            s += xv[j].x * g.x + xv[j].y * g.y + xv[j].z * g.z + xv[j].w * g.w;
        }
#pragma unroll
        for (int o = 16; o > 0; o >>= 1) s += __shfl_xor_sync(0xffffffffu, s, o);
        if (s > best) { best = s; bi = e; }
    }
    if (lane == 0) {
        g_expert[warp] = bi;
        g_pos[warp] = atomicAdd(&g_cnt[bi], 1);
    }
}

__global__ void build_tiles_kernel() {
    int off = 0;
    for (int e = 0; e < NEXP; e++) { g_off[e] = off; off += g_cnt[e]; }
    int nt = 0;
    for (int e = 0; e < NEXP; e++) {
        for (int r = 0; r < g_cnt[e]; r += 128) {
            g_tileE[nt] = e;
            g_tileRow[nt] = g_off[e] + r;
            g_tileCnt[nt] = min(128, g_cnt[e] - r);
            nt++;
        }
    }
    g_numTiles = nt;
}

__global__ void scatter_kernel() {
    int t = blockIdx.x * blockDim.x + threadIdx.x;
    if (t >= NTOK) return;
    g_perm[g_off[g_expert[t]] + g_pos[t]] = t;
}

// ===================== fused fp32 -> fp16 conversion =====================
// region boundaries in float4 units
#define C_X   524288L
#define C_SW1 786432L
#define C_SW2 1048576L
#define C_W1  3145728L
#define C_W3  5242880L
#define C_W2  7340032L

__global__ void cvt_all(const float* __restrict__ x,   const float* __restrict__ sw1,
                        const float* __restrict__ sw2, const float* __restrict__ w1,
                        const float* __restrict__ w3,  const float* __restrict__ w2) {
    long i = (long)blockIdx.x * blockDim.x + threadIdx.x;
    if (i >= C_W2) return;
    const float* src; __half* dst; long off;
    if (i < C_X)        { src = x;   dst = g_xh;   off = i; }
    else if (i < C_SW1) { src = sw1; dst = g_sw1h; off = i - C_X; }
    else if (i < C_SW2) { src = sw2; dst = g_sw2h; off = i - C_SW1; }
    else if (i < C_W1)  { src = w1;  dst = g_w1h;  off = i - C_SW2; }
    else if (i < C_W3)  { src = w3;  dst = g_w3h;  off = i - C_W1; }
    else                { src = w2;  dst = g_w2h;  off = i - C_W3; }
    float4 v = reinterpret_cast<const float4*>(src)[off];
    __half2 h0 = __floats2half2_rn(v.x, v.y);
    __half2 h1 = __floats2half2_rn(v.z, v.w);
    reinterpret_cast<__half2*>(dst)[off * 2 + 0] = h0;
    reinterpret_cast<__half2*>(dst)[off * 2 + 1] = h1;
}

__device__ __forceinline__ float gelu_exact(float v) {
    return 0.5f * v * (1.0f + erff(v * 0.70710678118654752f));
}
__device__ __forceinline__ float silu_f(float v) {
    return v / (1.0f + expf(-v));
}

// ===================== fp16 mma GEMM: CTA 128x128, warp 32x64, k-chunk 32 =====================
// MODE 0: Hsh = h(gelu(x @ sw1^T))      KD=512
// MODE 1: A1  = Xg @ w1[e]^T (fp32)     KD=512  (perm rows)
// MODE 2: Hrh = h(silu(A1)*(Xg@w3^T))   KD=512  (perm rows)
// MODE 3: out = Hsh @ sw2^T             KD=2048
// MODE 4: out[perm] += Hrh @ w2[e]^T    KD=2048
template<int MODE>
__global__ __launch_bounds__(256, 2)
void mma_gemm(float* __restrict__ out)
{
    constexpr int KD = (MODE <= 2) ? DDIM : IDIM;
    constexpr int NC = KD / 32;
    constexpr bool ROUTED = (MODE == 1 || MODE == 2 || MODE == 4);

    extern __shared__ __align__(16) char dyns[];
    __shared__ int s_rows[128];

    const __half* Asrc;
    if constexpr (MODE == 3)      Asrc = g_Hsh;
    else if constexpr (MODE == 4) Asrc = g_Hrh;
    else                          Asrc = g_xh;

    const __half* Bsrc;
    if constexpr (MODE == 0)      Bsrc = g_sw1h;
    else if constexpr (MODE == 1) Bsrc = g_w1h;
    else if constexpr (MODE == 2) Bsrc = g_w3h;
    else if constexpr (MODE == 3) Bsrc = g_sw2h;
    else                          Bsrc = g_w2h;

    int bx = blockIdx.x, by = blockIdx.y;
    int rowStart, rowCnt; int eid = 0;
    if constexpr (ROUTED) {
        if (bx >= g_numTiles) return;
        eid = g_tileE[bx]; rowStart = g_tileRow[bx]; rowCnt = g_tileCnt[bx];
    } else {
        rowStart = bx * 128; rowCnt = 128;
    }

    size_t bBase;
    if constexpr (MODE == 1 || MODE == 2) bBase = (size_t)eid * (IDIM * DDIM) + (size_t)(by * 128) * KD;
    else if constexpr (MODE == 4)         bBase = (size_t)eid * (DDIM * IDIM) + (size_t)(by * 128) * KD;
    else                                  bBase = (size_t)(by * 128) * KD;

    int tid = threadIdx.x;
    if (tid < 128) {
        int r = ROUTED ? min(tid, rowCnt - 1) : tid;
        int grow;
        if constexpr (MODE == 1 || MODE == 2) grow = g_perm[rowStart + r];
        else grow = rowStart + r;
        s_rows[tid] = grow;
    }
    __syncthreads();

    uint32_t dynB = smem_u32(dyns);

    auto load_stage = [&](int c) {
        if (c < NC) {
            int kk = c * 32;
            uint32_t sb = dynB + (uint32_t)((c % 3) * STG);
#pragma unroll
            for (int i = 0; i < 4; i++) {
                int g = i * 256 + tid;          // 0..1023
                int row2 = g >> 2;              // 0..255
                int seg = (g & 3) * 8;          // halves
                int isB = (row2 >= 128);
                int row = row2 & 127;
                uint32_t dst = sb + (uint32_t)(isB * 10240 + row * (SA * 2) + seg * 2);
                const __half* src = isB ? (Bsrc + bBase + (size_t)row * KD + kk + seg)
                                        : (Asrc + (size_t)s_rows[row] * KD + kk + seg);
                CP16(dst, src);
            }
        }
        CP_COMMIT();
    };

    int wid = tid >> 5, lane = tid & 31;
    int wm = (wid & 3) * 32;
    int wn = (wid >> 2) * 64;
    int aRow = (lane & 7) + ((lane >> 3) & 1) * 8;
    int aCol = (lane >> 4) * 8;
    int bRow = (lane & 7) + ((lane >> 4) & 1) * 8;
    int bCol = ((lane >> 3) & 1) * 8;

    float acc[2][8][4];
#pragma unroll
    for (int mf = 0; mf < 2; mf++)
#pragma unroll
        for (int nf = 0; nf < 8; nf++)
#pragma unroll
            for (int r = 0; r < 4; r++) acc[mf][nf][r] = 0.f;

    load_stage(0);
    load_stage(1);

    for (int c = 0; c < NC; ++c) {
        load_stage(c + 2);
        CP_WAIT2();
        __syncthreads();
        uint32_t sbA = dynB + (uint32_t)((c % 3) * STG);
        uint32_t sbB = sbA + 10240;
#pragma unroll
        for (int kb = 0; kb < 32; kb += 16) {
            uint32_t ah[2][4], bh[8][2];
#pragma unroll
            for (int mf = 0; mf < 2; mf++) {
                uint32_t off = (uint32_t)(((wm + mf * 16 + aRow) * SA + kb + aCol) * 2);
                LDSM4(ah[mf][0], ah[mf][1], ah[mf][2], ah[mf][3], sbA + off);
            }
#pragma unroll
            for (int n2 = 0; n2 < 4; n2++) {
                uint32_t off = (uint32_t)(((wn + n2 * 16 + bRow) * SA + kb + bCol) * 2);
                uint32_t r0, r1, r2, r3;
                LDSM4(r0, r1, r2, r3, sbB + off);
                bh[n2 * 2][0] = r0; bh[n2 * 2][1] = r1;
                bh[n2 * 2 + 1][0] = r2; bh[n2 * 2 + 1][1] = r3;
            }
#pragma unroll
            for (int mf = 0; mf < 2; mf++)
#pragma unroll
                for (int nf = 0; nf < 8; nf++)
                    MMAH(acc[mf][nf], ah[mf], bh[nf]);
        }
        __syncthreads();
    }

    // ---- epilogue (c-frag rows: lane>>2 (+8), cols: (lane&3)*2) ----
#pragma unroll
    for (int mf = 0; mf < 2; mf++) {
#pragma unroll
        for (int half = 0; half < 2; half++) {
            int mloc = wm + mf * 16 + (lane >> 2) + half * 8;
            if (ROUTED && mloc >= rowCnt) continue;
            int sp = rowStart + mloc;
#pragma unroll
            for (int nf = 0; nf < 8; nf++) {
                float v0 = acc[mf][nf][half * 2 + 0];
                float v1 = acc[mf][nf][half * 2 + 1];
                int colg = by * 128 + wn + nf * 8 + (lane & 3) * 2;
                if constexpr (MODE == 0) {
                    size_t o = (size_t)sp * IDIM + colg;
                    *reinterpret_cast<__half2*>(g_Hsh + o) =
                        __floats2half2_rn(gelu_exact(v0), gelu_exact(v1));
                } else if constexpr (MODE == 1) {
                    size_t o = (size_t)sp * IDIM + colg;
                    float2 v; v.x = v0; v.y = v1;
                    *reinterpret_cast<float2*>(g_A1 + o) = v;
                } else if constexpr (MODE == 2) {
                    size_t o = (size_t)sp * IDIM + colg;
                    float2 a1 = *reinterpret_cast<const float2*>(g_A1 + o);
                    *reinterpret_cast<__half2*>(g_Hrh + o) =
                        __floats2half2_rn(silu_f(a1.x) * v0, silu_f(a1.y) * v1);
                } else if constexpr (MODE == 3) {
                    size_t o = (size_t)sp * DDIM + colg;
                    float2 v; v.x = v0; v.y = v1;
                    *reinterpret_cast<float2*>(out + o) = v;
                } else {
                    int tok = g_perm[sp];
                    size_t o = (size_t)tok * DDIM + colg;
                    float2 v = *reinterpret_cast<const float2*>(out + o);
                    v.x += v0; v.y += v1;
                    *reinterpret_cast<float2*>(out + o) = v;
                }
            }
        }
    }
}

// ===================== launch =====================
extern "C" void kernel_launch(void* const* d_in, const int* in_sizes, int n_in,
                              void* d_out, int out_size) {
    const float* x   = (const float*)d_in[0];   // [4096, 512]
    const float* gw  = (const float*)d_in[1];   // [8, 512]
    const float* w1  = (const float*)d_in[2];   // [8, 2048, 512]
    const float* w2  = (const float*)d_in[3];   // [8, 512, 2048]
    const float* w3  = (const float*)d_in[4];   // [8, 2048, 512]
    const float* sw1 = (const float*)d_in[5];   // [2048, 512]
    const float* sw2 = (const float*)d_in[6];   // [512, 2048]
    float* out = (float*)d_out;                 // [4096, 512]

    cvt_all<<<(int)((C_W2 + 255) / 256), 256>>>(x, sw1, sw2, w1, w3, w2);

    zero_kernel<<<1, 32>>>();
    gate_kernel<<<NTOK / 8, 256>>>(x, gw);
    build_tiles_kernel<<<1, 1>>>();
    scatter_kernel<<<NTOK / 256, 256>>>();

    cudaFuncSetAttribute(mma_gemm<0>, cudaFuncAttributeMaxDynamicSharedMemorySize, SMEMSZ);
    cudaFuncSetAttribute(mma_gemm<1>, cudaFuncAttributeMaxDynamicSharedMemorySize, SMEMSZ);
    cudaFuncSetAttribute(mma_gemm<2>, cudaFuncAttributeMaxDynamicSharedMemorySize, SMEMSZ);
    cudaFuncSetAttribute(mma_gemm<3>, cudaFuncAttributeMaxDynamicSharedMemorySize, SMEMSZ);
    cudaFuncSetAttribute(mma_gemm<4>, cudaFuncAttributeMaxDynamicSharedMemorySize, SMEMSZ);

    mma_gemm<0><<<dim3(NTOK / 128, IDIM / 128), 256, SMEMSZ>>>(nullptr);
    mma_gemm<1><<<dim3(MAXTILES, IDIM / 128), 256, SMEMSZ>>>(nullptr);
    mma_gemm<2><<<dim3(MAXTILES, IDIM / 128), 256, SMEMSZ>>>(nullptr);
    mma_gemm<3><<<dim3(NTOK / 128, DDIM / 128), 256, SMEMSZ>>>(out);
    mma_gemm<4><<<dim3(MAXTILES, DDIM / 128), 256, SMEMSZ>>>(out);
}

// round 8
// speedup vs baseline: 1.6786x; 1.6786x over previous
#include <cuda_runtime.h>
#include <cuda_fp16.h>
#include <math.h>
#include <stdint.h>

#define NTOK 4096
#define DDIM 512
#define IDIM 2048
#define NEXP 8
#define SA 40                  // smem row stride in halves (80 B)
#define STG_UP 30720           // A + B1 + B3 (3 x 10240)
#define SM_UP (3 * STG_UP)     // 92160
#define STG_DN 20480           // A + B
#define SM_DN (3 * STG_DN)     // 61440

// ===================== device scratch =====================
__device__ int g_expert[NTOK];
__device__ int g_pos[NTOK];
__device__ int g_perm[NTOK];
__device__ int g_cnt[NEXP];
__device__ int g_off[NEXP];
__device__ int g_tileE[64];
__device__ int g_tileRow[64];
__device__ int g_tileCnt[64];
__device__ int g_numTiles;

__device__ __half g_Hsh[(size_t)NTOK * IDIM];
__device__ __half g_Hrh[(size_t)NTOK * IDIM];

__device__ __half g_xh[(size_t)NTOK * DDIM];
__device__ __half g_sw1h[(size_t)IDIM * DDIM];
__device__ __half g_sw2h[(size_t)DDIM * IDIM];
__device__ __half g_w1h[(size_t)NEXP * IDIM * DDIM];
__device__ __half g_w3h[(size_t)NEXP * IDIM * DDIM];
__device__ __half g_w2h[(size_t)NEXP * DDIM * IDIM];

// ===================== PTX helpers =====================
__device__ __forceinline__ uint32_t smem_u32(const void* p) {
    uint32_t a;
    asm("{ .reg .u64 t; cvta.to.shared.u64 t, %1; cvt.u32.u64 %0, t; }" : "=r"(a) : "l"(p));
    return a;
}
#define CP16(dst, src) asm volatile("cp.async.cg.shared.global [%0], [%1], 16;" :: "r"(dst), "l"(src))
#define CP_COMMIT()    asm volatile("cp.async.commit_group;" ::: "memory")
#define CP_WAIT2()     asm volatile("cp.async.wait_group 2;" ::: "memory")

#define LDSM4(r0, r1, r2, r3, a) \
    asm volatile("ldmatrix.sync.aligned.m8n8.x4.shared.b16 {%0,%1,%2,%3}, [%4];" \
        : "=r"(r0), "=r"(r1), "=r"(r2), "=r"(r3) : "r"(a))

#define MMAH(d, A, B) \
    asm volatile("mma.sync.aligned.m16n8k16.row.col.f32.f16.f16.f32 " \
        "{%0,%1,%2,%3},{%4,%5,%6,%7},{%8,%9},{%0,%1,%2,%3};" \
        : "+f"((d)[0]), "+f"((d)[1]), "+f"((d)[2]), "+f"((d)[3]) \
        : "r"((A)[0]), "r"((A)[1]), "r"((A)[2]), "r"((A)[3]), "r"((B)[0]), "r"((B)[1]))

// ===================== conversion + gate setup =====================
#define C_X   524288L
#define C_SW1 786432L
#define C_SW2 1048576L
#define C_W1  3145728L
#define C_W3  5242880L
#define C_W2  7340032L

__global__ void cvt_all(const float* __restrict__ x,   const float* __restrict__ sw1,
                        const float* __restrict__ sw2, const float* __restrict__ w1,
                        const float* __restrict__ w3,  const float* __restrict__ w2) {
    if (blockIdx.x == 0 && threadIdx.x < NEXP) g_cnt[threadIdx.x] = 0;
    long i = (long)blockIdx.x * blockDim.x + threadIdx.x;
    if (i >= C_W2) return;
    const float* src; __half* dst; long off;
    if (i < C_X)        { src = x;   dst = g_xh;   off = i; }
    else if (i < C_SW1) { src = sw1; dst = g_sw1h; off = i - C_X; }
    else if (i < C_SW2) { src = sw2; dst = g_sw2h; off = i - C_SW1; }
    else if (i < C_W1)  { src = w1;  dst = g_w1h;  off = i - C_SW2; }
    else if (i < C_W3)  { src = w3;  dst = g_w3h;  off = i - C_W1; }
    else                { src = w2;  dst = g_w2h;  off = i - C_W3; }
    float4 v = reinterpret_cast<const float4*>(src)[off];
    reinterpret_cast<__half2*>(dst)[off * 2 + 0] = __floats2half2_rn(v.x, v.y);
    reinterpret_cast<__half2*>(dst)[off * 2 + 1] = __floats2half2_rn(v.z, v.w);
}

__global__ void gate_kernel(const float* __restrict__ x, const float* __restrict__ gw) {
    int warp = (int)((blockIdx.x * blockDim.x + threadIdx.x) >> 5);
    int lane = threadIdx.x & 31;
    if (warp >= NTOK) return;
    const float4* xr = reinterpret_cast<const float4*>(x + (size_t)warp * DDIM + lane * 16);
    float4 xv[4];
#pragma unroll
    for (int j = 0; j < 4; j++) xv[j] = xr[j];
    float best = -1e30f; int bi = 0;
#pragma unroll
    for (int e = 0; e < NEXP; e++) {
        const float4* gr = reinterpret_cast<const float4*>(gw + (size_t)e * DDIM + lane * 16);
        float s = 0.f;
#pragma unroll
        for (int j = 0; j < 4; j++) {
            float4 g = gr[j];
            s += xv[j].x * g.x + xv[j].y * g.y + xv[j].z * g.z + xv[j].w * g.w;
        }
#pragma unroll
        for (int o = 16; o > 0; o >>= 1) s += __shfl_xor_sync(0xffffffffu, s, o);
        if (s > best) { best = s; bi = e; }
    }
    if (lane == 0) {
        g_expert[warp] = bi;
        g_pos[warp] = atomicAdd(&g_cnt[bi], 1);
    }
}

__global__ void build_scatter_kernel() {
    if (threadIdx.x == 0) {
        int off = 0;
        for (int e = 0; e < NEXP; e++) { g_off[e] = off; off += g_cnt[e]; }
        int nt = 0;
        for (int e = 0; e < NEXP; e++)
            for (int r = 0; r < g_cnt[e]; r += 128) {
                g_tileE[nt] = e;
                g_tileRow[nt] = g_off[e] + r;
                g_tileCnt[nt] = min(128, g_cnt[e] - r);
                nt++;
            }
        g_numTiles = nt;
    }
    __syncthreads();
    for (int t = threadIdx.x; t < NTOK; t += blockDim.x)
        g_perm[g_off[g_expert[t]] + g_pos[t]] = t;
}

__device__ __forceinline__ float gelu_exact(float v) {
    return 0.5f * v * (1.0f + erff(v * 0.70710678118654752f));
}
__device__ __forceinline__ float silu_f(float v) {
    return v / (1.0f + expf(-v));
}

// ===================== UP: fused shared-up + routed-up (w1&w3) =====================
// grid (72, 16), 512 thr. bx<32: Hsh = gelu(x @ sw1^T). bx>=32: tile bt=bx-32,
// Hrh = silu(Xg@w1^T) * (Xg@w3^T).  KD=512, CTA tile 128x128, warp 32x32 (x2 for routed).
__global__ __launch_bounds__(512, 1)
void up_kernel()
{
    constexpr int NC = DDIM / 32;
    extern __shared__ __align__(16) char dyns[];
    __shared__ int s_rows[128];

    int bx = blockIdx.x, by = blockIdx.y;
    bool routed = (bx >= 32);
    int rowStart, rowCnt; int eid = 0;
    if (routed) {
        int bt = bx - 32;
        if (bt >= g_numTiles) return;
        eid = g_tileE[bt]; rowStart = g_tileRow[bt]; rowCnt = g_tileCnt[bt];
    } else {
        rowStart = bx * 128; rowCnt = 128;
    }

    const __half* B1 = routed ? (g_w1h + (size_t)eid * (IDIM * DDIM) + (size_t)(by * 128) * DDIM)
                              : (g_sw1h + (size_t)(by * 128) * DDIM);
    const __half* B3 = g_w3h + (size_t)eid * (IDIM * DDIM) + (size_t)(by * 128) * DDIM;

    int tid = threadIdx.x;
    if (tid < 128) {
        int r = routed ? min(tid, rowCnt - 1) : tid;
        s_rows[tid] = routed ? g_perm[rowStart + r] : (rowStart + r);
    }
    __syncthreads();

    uint32_t dynB = smem_u32(dyns);

    auto load_stage = [&](int c) {
        if (c < NC) {
            int kk = c * 32;
            uint32_t sb = dynB + (uint32_t)((c % 3) * STG_UP);
#pragma unroll
            for (int i = 0; i < 3; i++) {
                int g = i * 512 + tid;
                int arr = g >> 9;            // 0=A 1=B1 2=B3
                if (arr == 2 && !routed) break;
                int idx = g & 511;
                int row = idx >> 2;
                int seg = (idx & 3) * 8;
                uint32_t dst = sb + (uint32_t)(arr * 10240 + row * (SA * 2) + seg * 2);
                const __half* src;
                if (arr == 0)      src = g_xh + (size_t)s_rows[row] * DDIM + kk + seg;
                else if (arr == 1) src = B1 + (size_t)row * DDIM + kk + seg;
                else               src = B3 + (size_t)row * DDIM + kk + seg;
                CP16(dst, src);
            }
        }
        CP_COMMIT();
    };

    int wid = tid >> 5, lane = tid & 31;
    int wm = (wid & 3) * 32;
    int wn = (wid >> 2) * 32;
    int aRow = (lane & 7) + ((lane >> 3) & 1) * 8;
    int aCol = (lane >> 4) * 8;
    int bRow = (lane & 7) + ((lane >> 4) & 1) * 8;
    int bCol = ((lane >> 3) & 1) * 8;

    float acc1[2][4][4], acc3[2][4][4];
#pragma unroll
    for (int mf = 0; mf < 2; mf++)
#pragma unroll
        for (int nf = 0; nf < 4; nf++)
#pragma unroll
            for (int r = 0; r < 4; r++) { acc1[mf][nf][r] = 0.f; acc3[mf][nf][r] = 0.f; }

    load_stage(0);
    load_stage(1);

    for (int c = 0; c < NC; ++c) {
        load_stage(c + 2);
        CP_WAIT2();
        __syncthreads();
        uint32_t sbA = dynB + (uint32_t)((c % 3) * STG_UP);
        uint32_t sbB1 = sbA + 10240;
        uint32_t sbB3 = sbA + 20480;
#pragma unroll
        for (int kb = 0; kb < 32; kb += 16) {
            uint32_t ah[2][4], bh1[4][2], bh3[4][2];
#pragma unroll
            for (int mf = 0; mf < 2; mf++) {
                uint32_t off = (uint32_t)(((wm + mf * 16 + aRow) * SA + kb + aCol) * 2);
                LDSM4(ah[mf][0], ah[mf][1], ah[mf][2], ah[mf][3], sbA + off);
            }
#pragma unroll
            for (int n2 = 0; n2 < 2; n2++) {
                uint32_t off = (uint32_t)(((wn + n2 * 16 + bRow) * SA + kb + bCol) * 2);
                uint32_t r0, r1, r2, r3;
                LDSM4(r0, r1, r2, r3, sbB1 + off);
                bh1[n2 * 2][0] = r0; bh1[n2 * 2][1] = r1;
                bh1[n2 * 2 + 1][0] = r2; bh1[n2 * 2 + 1][1] = r3;
            }
#pragma unroll
            for (int mf = 0; mf < 2; mf++)
#pragma unroll
                for (int nf = 0; nf < 4; nf++)
                    MMAH(acc1[mf][nf], ah[mf], bh1[nf]);
            if (routed) {
#pragma unroll
                for (int n2 = 0; n2 < 2; n2++) {
                    uint32_t off = (uint32_t)(((wn + n2 * 16 + bRow) * SA + kb + bCol) * 2);
                    uint32_t r0, r1, r2, r3;
                    LDSM4(r0, r1, r2, r3, sbB3 + off);
                    bh3[n2 * 2][0] = r0; bh3[n2 * 2][1] = r1;
                    bh3[n2 * 2 + 1][0] = r2; bh3[n2 * 2 + 1][1] = r3;
                }
#pragma unroll
                for (int mf = 0; mf < 2; mf++)
#pragma unroll
                    for (int nf = 0; nf < 4; nf++)
                        MMAH(acc3[mf][nf], ah[mf], bh3[nf]);
            }
        }
        __syncthreads();
    }

    // epilogue
#pragma unroll
    for (int mf = 0; mf < 2; mf++) {
#pragma unroll
        for (int half = 0; half < 2; half++) {
            int mloc = wm + mf * 16 + (lane >> 2) + half * 8;
            if (routed && mloc >= rowCnt) continue;
            int sp = rowStart + mloc;
#pragma unroll
            for (int nf = 0; nf < 4; nf++) {
                float v0 = acc1[mf][nf][half * 2 + 0];
                float v1 = acc1[mf][nf][half * 2 + 1];
                int colg = by * 128 + wn + nf * 8 + (lane & 3) * 2;
                size_t o = (size_t)sp * IDIM + colg;
                if (!routed) {
                    *reinterpret_cast<__half2*>(g_Hsh + o) =
                        __floats2half2_rn(gelu_exact(v0), gelu_exact(v1));
                } else {
                    float u0 = acc3[mf][nf][half * 2 + 0];
                    float u1 = acc3[mf][nf][half * 2 + 1];
                    *reinterpret_cast<__half2*>(g_Hrh + o) =
                        __floats2half2_rn(silu_f(v0) * u0, silu_f(v1) * u1);
                }
            }
        }
    }
}

// ===================== DOWN: fused shared-down + routed-down =====================
// grid (72, 4), 256 thr. bx<32: out += Hsh @ sw2^T.  bx>=32: out[perm] += Hrh @ w2[e]^T.
// out must be zeroed beforehand; both paths accumulate with atomicAdd.
__global__ __launch_bounds__(256, 2)
void down_kernel(float* __restrict__ out)
{
    constexpr int NC = IDIM / 32;
    extern __shared__ __align__(16) char dyns[];
    __shared__ int s_rows[128];

    int bx = blockIdx.x, by = blockIdx.y;
    bool routed = (bx >= 32);
    int rowStart, rowCnt; int eid = 0;
    if (routed) {
        int bt = bx - 32;
        if (bt >= g_numTiles) return;
        eid = g_tileE[bt]; rowStart = g_tileRow[bt]; rowCnt = g_tileCnt[bt];
    } else {
        rowStart = bx * 128; rowCnt = 128;
    }

    const __half* Asrc = routed ? g_Hrh : g_Hsh;
    const __half* Bsrc = routed ? (g_w2h + (size_t)eid * (DDIM * IDIM) + (size_t)(by * 128) * IDIM)
                                : (g_sw2h + (size_t)(by * 128) * IDIM);

    int tid = threadIdx.x;
    if (tid < 128) {
        int r = routed ? min(tid, rowCnt - 1) : tid;
        s_rows[tid] = rowStart + r;   // Hr rows are sorted positions; Hs rows are tokens
    }
    __syncthreads();

    uint32_t dynB = smem_u32(dyns);

    auto load_stage = [&](int c) {
        if (c < NC) {
            int kk = c * 32;
            uint32_t sb = dynB + (uint32_t)((c % 3) * STG_DN);
#pragma unroll
            for (int i = 0; i < 4; i++) {
                int g = i * 256 + tid;
                int row2 = g >> 2;
                int seg = (g & 3) * 8;
                int isB = (row2 >= 128);
                int row = row2 & 127;
                uint32_t dst = sb + (uint32_t)(isB * 10240 + row * (SA * 2) + seg * 2);
                const __half* src = isB ? (Bsrc + (size_t)row * IDIM + kk + seg)
                                        : (Asrc + (size_t)s_rows[row] * IDIM + kk + seg);
                CP16(dst, src);
            }
        }
        CP_COMMIT();
    };

    int wid = tid >> 5, lane = tid & 31;
    int wm = (wid & 3) * 32;
    int wn = (wid >> 2) * 64;
    int aRow = (lane & 7) + ((lane >> 3) & 1) * 8;
    int aCol = (lane >> 4) * 8;
    int bRow = (lane & 7) + ((lane >> 4) & 1) * 8;
    int bCol = ((lane >> 3) & 1) * 8;

    float acc[2][8][4];
#pragma unroll
    for (int mf = 0; mf < 2; mf++)
#pragma unroll
        for (int nf = 0; nf < 8; nf++)
#pragma unroll
            for (int r = 0; r < 4; r++) acc[mf][nf][r] = 0.f;

    load_stage(0);
    load_stage(1);

    for (int c = 0; c < NC; ++c) {
        load_stage(c + 2);
        CP_WAIT2();
        __syncthreads();
        uint32_t sbA = dynB + (uint32_t)((c % 3) * STG_DN);
        uint32_t sbB = sbA + 10240;
#pragma unroll
        for (int kb = 0; kb < 32; kb += 16) {
            uint32_t ah[2][4], bh[8][2];
#pragma unroll
            for (int mf = 0; mf < 2; mf++) {
                uint32_t off = (uint32_t)(((wm + mf * 16 + aRow) * SA + kb + aCol) * 2);
                LDSM4(ah[mf][0], ah[mf][1], ah[mf][2], ah[mf][3], sbA + off);
            }
#pragma unroll
            for (int n2 = 0; n2 < 4; n2++) {
                uint32_t off = (uint32_t)(((wn + n2 * 16 + bRow) * SA + kb + bCol) * 2);
                uint32_t r0, r1, r2, r3;
                LDSM4(r0, r1, r2, r3, sbB + off);
                bh[n2 * 2][0] = r0; bh[n2 * 2][1] = r1;
                bh[n2 * 2 + 1][0] = r2; bh[n2 * 2 + 1][1] = r3;
            }
#pragma unroll
            for (int mf = 0; mf < 2; mf++)
#pragma unroll
                for (int nf = 0; nf < 8; nf++)
                    MMAH(acc[mf][nf], ah[mf], bh[nf]);
        }
        __syncthreads();
    }

    // epilogue: accumulate into out
#pragma unroll
    for (int mf = 0; mf < 2; mf++) {
#pragma unroll
        for (int half = 0; half < 2; half++) {
            int mloc = wm + mf * 16 + (lane >> 2) + half * 8;
            if (routed && mloc >= rowCnt) continue;
            int sp = rowStart + mloc;
            int tok = routed ? g_perm[sp] : sp;
            float* orow = out + (size_t)tok * DDIM;
#pragma unroll
            for (int nf = 0; nf < 8; nf++) {
                int colg = by * 128 + wn + nf * 8 + (lane & 3) * 2;
                atomicAdd(orow + colg,     acc[mf][nf][half * 2 + 0]);
                atomicAdd(orow + colg + 1, acc[mf][nf][half * 2 + 1]);
            }
        }
    }
}

// ===================== launch =====================
extern "C" void kernel_launch(void* const* d_in, const int* in_sizes, int n_in,
                              void* d_out, int out_size) {
    const float* x   = (const float*)d_in[0];   // [4096, 512]
    const float* gw  = (const float*)d_in[1];   // [8, 512]
    const float* w1  = (const float*)d_in[2];   // [8, 2048, 512]
    const float* w2  = (const float*)d_in[3];   // [8, 512, 2048]
    const float* w3  = (const float*)d_in[4];   // [8, 2048, 512]
    const float* sw1 = (const float*)d_in[5];   // [2048, 512]
    const float* sw2 = (const float*)d_in[6];   // [512, 2048]
    float* out = (float*)d_out;                 // [4096, 512]

    cudaMemsetAsync(out, 0, (size_t)out_size * sizeof(float));
    cvt_all<<<(int)((C_W2 + 255) / 256), 256>>>(x, sw1, sw2, w1, w3, w2);
    gate_kernel<<<NTOK / 8, 256>>>(x, gw);
    build_scatter_kernel<<<1, 256>>>();

    cudaFuncSetAttribute(up_kernel,   cudaFuncAttributeMaxDynamicSharedMemorySize, SM_UP);
    cudaFuncSetAttribute(down_kernel, cudaFuncAttributeMaxDynamicSharedMemorySize, SM_DN);

    up_kernel<<<dim3(72, 16), 512, SM_UP>>>();
    down_kernel<<<dim3(72, 4), 256, SM_DN>>>(out);
}

// round 9
// speedup vs baseline: 1.7832x; 1.0623x over previous
#include <cuda_runtime.h>
#include <cuda_fp16.h>
#include <math.h>
#include <stdint.h>

#define NTOK 4096
#define DDIM 512
#define IDIM 2048
#define NEXP 8
#define SA 40                  // smem row stride in halves (80 B)
#define STG_UP 20480           // A(128x80B) + B1(64x80B) + B3(64x80B)
#define SM_UP (3 * STG_UP)     // 61440
#define STG_DN 20480           // A(128) + B(128)
#define SM_DN (3 * STG_DN)     // 61440

// ===================== device scratch =====================
__device__ int g_expert[NTOK];
__device__ int g_pos[NTOK];
__device__ int g_perm[NTOK];
__device__ int g_cnt[NEXP];
__device__ int g_off[NEXP];
__device__ int g_tileE[64];
__device__ int g_tileRow[64];
__device__ int g_tileCnt[64];
__device__ int g_numTiles;

__device__ __half g_Hsh[(size_t)NTOK * IDIM];
__device__ __half g_Hrh[(size_t)NTOK * IDIM];

__device__ __half g_xh[(size_t)NTOK * DDIM];
__device__ __half g_sw1h[(size_t)IDIM * DDIM];
__device__ __half g_sw2h[(size_t)DDIM * IDIM];
__device__ __half g_w1h[(size_t)NEXP * IDIM * DDIM];
__device__ __half g_w3h[(size_t)NEXP * IDIM * DDIM];
__device__ __half g_w2h[(size_t)NEXP * DDIM * IDIM];

// ===================== PTX helpers =====================
__device__ __forceinline__ uint32_t smem_u32(const void* p) {
    uint32_t a;
    asm("{ .reg .u64 t; cvta.to.shared.u64 t, %1; cvt.u32.u64 %0, t; }" : "=r"(a) : "l"(p));
    return a;
}
#define CP16(dst, src) asm volatile("cp.async.cg.shared.global [%0], [%1], 16;" :: "r"(dst), "l"(src))
#define CP_COMMIT()    asm volatile("cp.async.commit_group;" ::: "memory")
#define CP_WAIT2()     asm volatile("cp.async.wait_group 2;" ::: "memory")

#define LDSM4(r0, r1, r2, r3, a) \
    asm volatile("ldmatrix.sync.aligned.m8n8.x4.shared.b16 {%0,%1,%2,%3}, [%4];" \
        : "=r"(r0), "=r"(r1), "=r"(r2), "=r"(r3) : "r"(a))

#define MMAH(d, A, B) \
    asm volatile("mma.sync.aligned.m16n8k16.row.col.f32.f16.f16.f32 " \
        "{%0,%1,%2,%3},{%4,%5,%6,%7},{%8,%9},{%0,%1,%2,%3};" \
        : "+f"((d)[0]), "+f"((d)[1]), "+f"((d)[2]), "+f"((d)[3]) \
        : "r"((A)[0]), "r"((A)[1]), "r"((A)[2]), "r"((A)[3]), "r"((B)[0]), "r"((B)[1]))

// ===================== conversion + gate setup =====================
#define C_X   524288L
#define C_SW1 786432L
#define C_SW2 1048576L
#define C_W1  3145728L
#define C_W3  5242880L
#define C_W2  7340032L

__global__ void cvt_all(const float* __restrict__ x,   const float* __restrict__ sw1,
                        const float* __restrict__ sw2, const float* __restrict__ w1,
                        const float* __restrict__ w3,  const float* __restrict__ w2) {
    if (blockIdx.x == 0 && threadIdx.x < NEXP) g_cnt[threadIdx.x] = 0;
    long i = (long)blockIdx.x * blockDim.x + threadIdx.x;
    if (i >= C_W2) return;
    const float* src; __half* dst; long off;
    if (i < C_X)        { src = x;   dst = g_xh;   off = i; }
    else if (i < C_SW1) { src = sw1; dst = g_sw1h; off = i - C_X; }
    else if (i < C_SW2) { src = sw2; dst = g_sw2h; off = i - C_SW1; }
    else if (i < C_W1)  { src = w1;  dst = g_w1h;  off = i - C_SW2; }
    else if (i < C_W3)  { src = w3;  dst = g_w3h;  off = i - C_W1; }
    else                { src = w2;  dst = g_w2h;  off = i - C_W3; }
    float4 v = reinterpret_cast<const float4*>(src)[off];
    reinterpret_cast<__half2*>(dst)[off * 2 + 0] = __floats2half2_rn(v.x, v.y);
    reinterpret_cast<__half2*>(dst)[off * 2 + 1] = __floats2half2_rn(v.z, v.w);
}

__global__ void gate_kernel(const float* __restrict__ x, const float* __restrict__ gw) {
    int warp = (int)((blockIdx.x * blockDim.x + threadIdx.x) >> 5);
    int lane = threadIdx.x & 31;
    if (warp >= NTOK) return;
    const float4* xr = reinterpret_cast<const float4*>(x + (size_t)warp * DDIM + lane * 16);
    float4 xv[4];
#pragma unroll
    for (int j = 0; j < 4; j++) xv[j] = xr[j];
    float best = -1e30f; int bi = 0;
#pragma unroll
    for (int e = 0; e < NEXP; e++) {
        const float4* gr = reinterpret_cast<const float4*>(gw + (size_t)e * DDIM + lane * 16);
        float s = 0.f;
#pragma unroll
        for (int j = 0; j < 4; j++) {
            float4 g = gr[j];
            s += xv[j].x * g.x + xv[j].y * g.y + xv[j].z * g.z + xv[j].w * g.w;
        }
#pragma unroll
        for (int o = 16; o > 0; o >>= 1) s += __shfl_xor_sync(0xffffffffu, s, o);
        if (s > best) { best = s; bi = e; }
    }
    if (lane == 0) {
        g_expert[warp] = bi;
        g_pos[warp] = atomicAdd(&g_cnt[bi], 1);
    }
}

__global__ void build_scatter_kernel() {
    if (threadIdx.x == 0) {
        int off = 0;
        for (int e = 0; e < NEXP; e++) { g_off[e] = off; off += g_cnt[e]; }
        int nt = 0;
        for (int e = 0; e < NEXP; e++)
            for (int r = 0; r < g_cnt[e]; r += 128) {
                g_tileE[nt] = e;
                g_tileRow[nt] = g_off[e] + r;
                g_tileCnt[nt] = min(128, g_cnt[e] - r);
                nt++;
            }
        g_numTiles = nt;
    }
    __syncthreads();
    for (int t = threadIdx.x; t < NTOK; t += blockDim.x)
        g_perm[g_off[g_expert[t]] + g_pos[t]] = t;
}

__device__ __forceinline__ float gelu_exact(float v) {
    return 0.5f * v * (1.0f + erff(v * 0.70710678118654752f));
}
__device__ __forceinline__ float silu_f(float v) {
    return v / (1.0f + expf(-v));
}

// ===================== UP: fused shared-up + routed-up (w1&w3), 256 thr, M128xN64 =====================
// grid (72, 32). bx<32: Hsh = gelu(x @ sw1^T). bx>=32: Hrh = silu(Xg@w1^T)*(Xg@w3^T).
__global__ __launch_bounds__(256, 2)
void up_kernel()
{
    constexpr int NC = DDIM / 32;
    extern __shared__ __align__(16) char dyns[];
    __shared__ int s_rows[128];

    int bx = blockIdx.x, by = blockIdx.y;
    bool routed = (bx >= 32);
    int rowStart, rowCnt; int eid = 0;
    if (routed) {
        int bt = bx - 32;
        if (bt >= g_numTiles) return;
        eid = g_tileE[bt]; rowStart = g_tileRow[bt]; rowCnt = g_tileCnt[bt];
    } else {
        rowStart = bx * 128; rowCnt = 128;
    }

    const __half* B1 = routed ? (g_w1h + (size_t)eid * (IDIM * DDIM) + (size_t)(by * 64) * DDIM)
                              : (g_sw1h + (size_t)(by * 64) * DDIM);
    const __half* B3 = g_w3h + (size_t)eid * (IDIM * DDIM) + (size_t)(by * 64) * DDIM;

    int tid = threadIdx.x;
    if (tid < 128) {
        int r = routed ? min(tid, rowCnt - 1) : tid;
        s_rows[tid] = routed ? g_perm[rowStart + r] : (rowStart + r);
    }
    __syncthreads();

    uint32_t dynB = smem_u32(dyns);

    auto load_stage = [&](int c) {
        if (c < NC) {
            int kk = c * 32;
            uint32_t sb = dynB + (uint32_t)((c % 3) * STG_UP);
#pragma unroll
            for (int i = 0; i < 4; i++) {
                int g = i * 256 + tid;        // 0..1023
                int row2 = g >> 2;            // 0..255: A rows 0..127, B1 128..191, B3 192..255
                int seg = (g & 3) * 8;
                if (row2 >= 192 && !routed) continue;
                uint32_t dst = sb + (uint32_t)(row2 * (SA * 2) + seg * 2);
                const __half* src;
                if (row2 < 128)      src = g_xh + (size_t)s_rows[row2] * DDIM + kk + seg;
                else if (row2 < 192) src = B1 + (size_t)(row2 - 128) * DDIM + kk + seg;
                else                 src = B3 + (size_t)(row2 - 192) * DDIM + kk + seg;
                CP16(dst, src);
            }
        }
        CP_COMMIT();
    };

    int wid = tid >> 5, lane = tid & 31;
    int wm = (wid & 3) * 32;
    int wn = (wid >> 2) * 32;
    int aRow = (lane & 7) + ((lane >> 3) & 1) * 8;
    int aCol = (lane >> 4) * 8;
    int bRow = (lane & 7) + ((lane >> 4) & 1) * 8;
    int bCol = ((lane >> 3) & 1) * 8;

    float acc1[2][4][4], acc3[2][4][4];
#pragma unroll
    for (int mf = 0; mf < 2; mf++)
#pragma unroll
        for (int nf = 0; nf < 4; nf++)
#pragma unroll
            for (int r = 0; r < 4; r++) { acc1[mf][nf][r] = 0.f; acc3[mf][nf][r] = 0.f; }

    load_stage(0);
    load_stage(1);

    for (int c = 0; c < NC; ++c) {
        load_stage(c + 2);
        CP_WAIT2();
        __syncthreads();
        uint32_t sbA = dynB + (uint32_t)((c % 3) * STG_UP);
        uint32_t sbB1 = sbA + 10240;
        uint32_t sbB3 = sbA + 15360;
#pragma unroll
        for (int kb = 0; kb < 32; kb += 16) {
            uint32_t ah[2][4], bh1[4][2], bh3[4][2];
#pragma unroll
            for (int mf = 0; mf < 2; mf++) {
                uint32_t off = (uint32_t)(((wm + mf * 16 + aRow) * SA + kb + aCol) * 2);
                LDSM4(ah[mf][0], ah[mf][1], ah[mf][2], ah[mf][3], sbA + off);
            }
#pragma unroll
            for (int n2 = 0; n2 < 2; n2++) {
                uint32_t off = (uint32_t)(((wn + n2 * 16 + bRow) * SA + kb + bCol) * 2);
                uint32_t r0, r1, r2, r3;
                LDSM4(r0, r1, r2, r3, sbB1 + off);
                bh1[n2 * 2][0] = r0; bh1[n2 * 2][1] = r1;
                bh1[n2 * 2 + 1][0] = r2; bh1[n2 * 2 + 1][1] = r3;
            }
#pragma unroll
            for (int mf = 0; mf < 2; mf++)
#pragma unroll
                for (int nf = 0; nf < 4; nf++)
                    MMAH(acc1[mf][nf], ah[mf], bh1[nf]);
            if (routed) {
#pragma unroll
                for (int n2 = 0; n2 < 2; n2++) {
                    uint32_t off = (uint32_t)(((wn + n2 * 16 + bRow) * SA + kb + bCol) * 2);
                    uint32_t r0, r1, r2, r3;
                    LDSM4(r0, r1, r2, r3, sbB3 + off);
                    bh3[n2 * 2][0] = r0; bh3[n2 * 2][1] = r1;
                    bh3[n2 * 2 + 1][0] = r2; bh3[n2 * 2 + 1][1] = r3;
                }
#pragma unroll
                for (int mf = 0; mf < 2; mf++)
#pragma unroll
                    for (int nf = 0; nf < 4; nf++)
                        MMAH(acc3[mf][nf], ah[mf], bh3[nf]);
            }
        }
        __syncthreads();
    }

    // epilogue
#pragma unroll
    for (int mf = 0; mf < 2; mf++) {
#pragma unroll
        for (int half = 0; half < 2; half++) {
            int mloc = wm + mf * 16 + (lane >> 2) + half * 8;
            if (routed && mloc >= rowCnt) continue;
            int sp = rowStart + mloc;
#pragma unroll
            for (int nf = 0; nf < 4; nf++) {
                float v0 = acc1[mf][nf][half * 2 + 0];
                float v1 = acc1[mf][nf][half * 2 + 1];
                int colg = by * 64 + wn + nf * 8 + (lane & 3) * 2;
                size_t o = (size_t)sp * IDIM + colg;
                if (!routed) {
                    *reinterpret_cast<__half2*>(g_Hsh + o) =
                        __floats2half2_rn(gelu_exact(v0), gelu_exact(v1));
                } else {
                    float u0 = acc3[mf][nf][half * 2 + 0];
                    float u1 = acc3[mf][nf][half * 2 + 1];
                    *reinterpret_cast<__half2*>(g_Hrh + o) =
                        __floats2half2_rn(silu_f(v0) * u0, silu_f(v1) * u1);
                }
            }
        }
    }
}

// ===================== DOWN: fused shared-down + routed-down =====================
// grid (72, 4), 256 thr. bx<32: out += Hsh @ sw2^T.  bx>=32: out[perm] += Hrh @ w2[e]^T.
__global__ __launch_bounds__(256, 2)
void down_kernel(float* __restrict__ out)
{
    constexpr int NC = IDIM / 32;
    extern __shared__ __align__(16) char dyns[];
    __shared__ int s_rows[128];

    int bx = blockIdx.x, by = blockIdx.y;
    bool routed = (bx >= 32);
    int rowStart, rowCnt; int eid = 0;
    if (routed) {
        int bt = bx - 32;
        if (bt >= g_numTiles) return;
        eid = g_tileE[bt]; rowStart = g_tileRow[bt]; rowCnt = g_tileCnt[bt];
    } else {
        rowStart = bx * 128; rowCnt = 128;
    }

    const __half* Asrc = routed ? g_Hrh : g_Hsh;
    const __half* Bsrc = routed ? (g_w2h + (size_t)eid * (DDIM * IDIM) + (size_t)(by * 128) * IDIM)
                                : (g_sw2h + (size_t)(by * 128) * IDIM);

    int tid = threadIdx.x;
    if (tid < 128) {
        int r = routed ? min(tid, rowCnt - 1) : tid;
        s_rows[tid] = rowStart + r;
    }
    __syncthreads();

    uint32_t dynB = smem_u32(dyns);

    auto load_stage = [&](int c) {
        if (c < NC) {
            int kk = c * 32;
            uint32_t sb = dynB + (uint32_t)((c % 3) * STG_DN);
#pragma unroll
            for (int i = 0; i < 4; i++) {
                int g = i * 256 + tid;
                int row2 = g >> 2;
                int seg = (g & 3) * 8;
                int isB = (row2 >= 128);
                int row = row2 & 127;
                uint32_t dst = sb + (uint32_t)(isB * 10240 + row * (SA * 2) + seg * 2);
                const __half* src = isB ? (Bsrc + (size_t)row * IDIM + kk + seg)
                                        : (Asrc + (size_t)s_rows[row] * IDIM + kk + seg);
                CP16(dst, src);
            }
        }
        CP_COMMIT();
    };

    int wid = tid >> 5, lane = tid & 31;
    int wm = (wid & 3) * 32;
    int wn = (wid >> 2) * 64;
    int aRow = (lane & 7) + ((lane >> 3) & 1) * 8;
    int aCol = (lane >> 4) * 8;
    int bRow = (lane & 7) + ((lane >> 4) & 1) * 8;
    int bCol = ((lane >> 3) & 1) * 8;

    float acc[2][8][4];
#pragma unroll
    for (int mf = 0; mf < 2; mf++)
#pragma unroll
        for (int nf = 0; nf < 8; nf++)
#pragma unroll
            for (int r = 0; r < 4; r++) acc[mf][nf][r] = 0.f;

    load_stage(0);
    load_stage(1);

    for (int c = 0; c < NC; ++c) {
        load_stage(c + 2);
        CP_WAIT2();
        __syncthreads();
        uint32_t sbA = dynB + (uint32_t)((c % 3) * STG_DN);
        uint32_t sbB = sbA + 10240;
#pragma unroll
        for (int kb = 0; kb < 32; kb += 16) {
            uint32_t ah[2][4], bh[8][2];
#pragma unroll
            for (int mf = 0; mf < 2; mf++) {
                uint32_t off = (uint32_t)(((wm + mf * 16 + aRow) * SA + kb + aCol) * 2);
                LDSM4(ah[mf][0], ah[mf][1], ah[mf][2], ah[mf][3], sbA + off);
            }
#pragma unroll
            for (int n2 = 0; n2 < 4; n2++) {
                uint32_t off = (uint32_t)(((wn + n2 * 16 + bRow) * SA + kb + bCol) * 2);
                uint32_t r0, r1, r2, r3;
                LDSM4(r0, r1, r2, r3, sbB + off);
                bh[n2 * 2][0] = r0; bh[n2 * 2][1] = r1;
                bh[n2 * 2 + 1][0] = r2; bh[n2 * 2 + 1][1] = r3;
            }
#pragma unroll
            for (int mf = 0; mf < 2; mf++)
#pragma unroll
                for (int nf = 0; nf < 8; nf++)
                    MMAH(acc[mf][nf], ah[mf], bh[nf]);
        }
        __syncthreads();
    }

#pragma unroll
    for (int mf = 0; mf < 2; mf++) {
#pragma unroll
        for (int half = 0; half < 2; half++) {
            int mloc = wm + mf * 16 + (lane >> 2) + half * 8;
            if (routed && mloc >= rowCnt) continue;
            int sp = rowStart + mloc;
            int tok = routed ? g_perm[sp] : sp;
            float* orow = out + (size_t)tok * DDIM;
#pragma unroll
            for (int nf = 0; nf < 8; nf++) {
                int colg = by * 128 + wn + nf * 8 + (lane & 3) * 2;
                atomicAdd(orow + colg,     acc[mf][nf][half * 2 + 0]);
                atomicAdd(orow + colg + 1, acc[mf][nf][half * 2 + 1]);
            }
        }
    }
}

// ===================== launch =====================
extern "C" void kernel_launch(void* const* d_in, const int* in_sizes, int n_in,
                              void* d_out, int out_size) {
    const float* x   = (const float*)d_in[0];   // [4096, 512]
    const float* gw  = (const float*)d_in[1];   // [8, 512]
    const float* w1  = (const float*)d_in[2];   // [8, 2048, 512]
    const float* w2  = (const float*)d_in[3];   // [8, 512, 2048]
    const float* w3  = (const float*)d_in[4];   // [8, 2048, 512]
    const float* sw1 = (const float*)d_in[5];   // [2048, 512]
    const float* sw2 = (const float*)d_in[6];   // [512, 2048]
    float* out = (float*)d_out;                 // [4096, 512]

    cudaMemsetAsync(out, 0, (size_t)out_size * sizeof(float));
    cvt_all<<<(int)((C_W2 + 255) / 256), 256>>>(x, sw1, sw2, w1, w3, w2);
    gate_kernel<<<NTOK / 8, 256>>>(x, gw);
    build_scatter_kernel<<<1, 256>>>();

    cudaFuncSetAttribute(up_kernel,   cudaFuncAttributeMaxDynamicSharedMemorySize, SM_UP);
    cudaFuncSetAttribute(down_kernel, cudaFuncAttributeMaxDynamicSharedMemorySize, SM_DN);

    up_kernel<<<dim3(72, IDIM / 64), 256, SM_UP>>>();
    down_kernel<<<dim3(72, 4), 256, SM_DN>>>(out);
}

// round 10
// speedup vs baseline: 1.9407x; 1.0883x over previous
#include <cuda_runtime.h>
#include <cuda_fp16.h>
#include <math.h>
#include <stdint.h>

#define NTOK 4096
#define DDIM 512
#define IDIM 2048
#define NEXP 8
#define SROW 72                // smem row stride in halves (144 B), k-chunk 64
#define STG_UP 36864           // (128 + 64 + 64) rows * 144 B
#define SM_UP (2 * STG_UP)     // 73728
#define STG_DN 36864           // (128 + 128) rows * 144 B
#define SM_DN (2 * STG_DN)     // 73728

// ===================== device scratch =====================
__device__ int g_expert[NTOK];
__device__ int g_pos[NTOK];
__device__ int g_perm[NTOK];
__device__ int g_cnt[NEXP];
__device__ int g_off[NEXP];
__device__ int g_tileE[64];
__device__ int g_tileRow[64];
__device__ int g_tileCnt[64];
__device__ int g_numTiles;

__device__ __half g_Hsh[(size_t)NTOK * IDIM];
__device__ __half g_Hrh[(size_t)NTOK * IDIM];

__device__ __half g_xh[(size_t)NTOK * DDIM];
__device__ __half g_sw1h[(size_t)IDIM * DDIM];
__device__ __half g_sw2h[(size_t)DDIM * IDIM];
__device__ __half g_w1h[(size_t)NEXP * IDIM * DDIM];
__device__ __half g_w3h[(size_t)NEXP * IDIM * DDIM];
__device__ __half g_w2h[(size_t)NEXP * DDIM * IDIM];

// ===================== PTX helpers =====================
__device__ __forceinline__ uint32_t smem_u32(const void* p) {
    uint32_t a;
    asm("{ .reg .u64 t; cvta.to.shared.u64 t, %1; cvt.u32.u64 %0, t; }" : "=r"(a) : "l"(p));
    return a;
}
#define CP16(dst, src) asm volatile("cp.async.cg.shared.global [%0], [%1], 16;" :: "r"(dst), "l"(src))
#define CP_COMMIT()    asm volatile("cp.async.commit_group;" ::: "memory")
#define CP_WAIT1()     asm volatile("cp.async.wait_group 1;" ::: "memory")

#define LDSM4(r0, r1, r2, r3, a) \
    asm volatile("ldmatrix.sync.aligned.m8n8.x4.shared.b16 {%0,%1,%2,%3}, [%4];" \
        : "=r"(r0), "=r"(r1), "=r"(r2), "=r"(r3) : "r"(a))

#define MMAH(d, A, B) \
    asm volatile("mma.sync.aligned.m16n8k16.row.col.f32.f16.f16.f32 " \
        "{%0,%1,%2,%3},{%4,%5,%6,%7},{%8,%9},{%0,%1,%2,%3};" \
        : "+f"((d)[0]), "+f"((d)[1]), "+f"((d)[2]), "+f"((d)[3]) \
        : "r"((A)[0]), "r"((A)[1]), "r"((A)[2]), "r"((A)[3]), "r"((B)[0]), "r"((B)[1]))

// ===================== conversion + gate setup =====================
#define C_X   524288L
#define C_SW1 786432L
#define C_SW2 1048576L
#define C_W1  3145728L
#define C_W3  5242880L
#define C_W2  7340032L

__global__ void cvt_all(const float* __restrict__ x,   const float* __restrict__ sw1,
                        const float* __restrict__ sw2, const float* __restrict__ w1,
                        const float* __restrict__ w3,  const float* __restrict__ w2) {
    if (blockIdx.x == 0 && threadIdx.x < NEXP) g_cnt[threadIdx.x] = 0;
    long i = (long)blockIdx.x * blockDim.x + threadIdx.x;
    if (i >= C_W2) return;
    const float* src; __half* dst; long off;
    if (i < C_X)        { src = x;   dst = g_xh;   off = i; }
    else if (i < C_SW1) { src = sw1; dst = g_sw1h; off = i - C_X; }
    else if (i < C_SW2) { src = sw2; dst = g_sw2h; off = i - C_SW1; }
    else if (i < C_W1)  { src = w1;  dst = g_w1h;  off = i - C_SW2; }
    else if (i < C_W3)  { src = w3;  dst = g_w3h;  off = i - C_W1; }
    else                { src = w2;  dst = g_w2h;  off = i - C_W3; }
    float4 v = reinterpret_cast<const float4*>(src)[off];
    reinterpret_cast<__half2*>(dst)[off * 2 + 0] = __floats2half2_rn(v.x, v.y);
    reinterpret_cast<__half2*>(dst)[off * 2 + 1] = __floats2half2_rn(v.z, v.w);
}

__global__ void gate_kernel(const float* __restrict__ x, const float* __restrict__ gw) {
    int warp = (int)((blockIdx.x * blockDim.x + threadIdx.x) >> 5);
    int lane = threadIdx.x & 31;
    if (warp >= NTOK) return;
    const float4* xr = reinterpret_cast<const float4*>(x + (size_t)warp * DDIM + lane * 16);
    float4 xv[4];
#pragma unroll
    for (int j = 0; j < 4; j++) xv[j] = xr[j];
    float best = -1e30f; int bi = 0;
#pragma unroll
    for (int e = 0; e < NEXP; e++) {
        const float4* gr = reinterpret_cast<const float4*>(gw + (size_t)e * DDIM + lane * 16);
        float s = 0.f;
#pragma unroll
        for (int j = 0; j < 4; j++) {
            float4 g = gr[j];
            s += xv[j].x * g.x + xv[j].y * g.y + xv[j].z * g.z + xv[j].w * g.w;
        }
#pragma unroll
        for (int o = 16; o > 0; o >>= 1) s += __shfl_xor_sync(0xffffffffu, s, o);
        if (s > best) { best = s; bi = e; }
    }
    if (lane == 0) {
        g_expert[warp] = bi;
        g_pos[warp] = atomicAdd(&g_cnt[bi], 1);
    }
}

__global__ void build_scatter_kernel() {
    if (threadIdx.x == 0) {
        int off = 0;
        for (int e = 0; e < NEXP; e++) { g_off[e] = off; off += g_cnt[e]; }
        int nt = 0;
        for (int e = 0; e < NEXP; e++)
            for (int r = 0; r < g_cnt[e]; r += 128) {
                g_tileE[nt] = e;
                g_tileRow[nt] = g_off[e] + r;
                g_tileCnt[nt] = min(128, g_cnt[e] - r);
                nt++;
            }
        g_numTiles = nt;
    }
    __syncthreads();
    for (int t = threadIdx.x; t < NTOK; t += blockDim.x)
        g_perm[g_off[g_expert[t]] + g_pos[t]] = t;
}

__device__ __forceinline__ float gelu_exact(float v) {
    return 0.5f * v * (1.0f + erff(v * 0.70710678118654752f));
}
__device__ __forceinline__ float silu_f(float v) {
    return v / (1.0f + expf(-v));
}

// ===================== UP: fused shared-up + routed-up (w1&w3), 256 thr, M128xN64, k-chunk 64 =====================
// grid (72, 32). bx<32: Hsh = gelu(x @ sw1^T). bx>=32: Hrh = silu(Xg@w1^T)*(Xg@w3^T).
__global__ __launch_bounds__(256, 2)
void up_kernel()
{
    constexpr int NC = DDIM / 64;   // 8
    extern __shared__ __align__(16) char dyns[];
    __shared__ int s_rows[128];

    int bx = blockIdx.x, by = blockIdx.y;
    bool routed = (bx >= 32);
    int rowStart, rowCnt; int eid = 0;
    if (routed) {
        int bt = bx - 32;
        if (bt >= g_numTiles) return;
        eid = g_tileE[bt]; rowStart = g_tileRow[bt]; rowCnt = g_tileCnt[bt];
    } else {
        rowStart = bx * 128; rowCnt = 128;
    }

    const __half* B1 = routed ? (g_w1h + (size_t)eid * (IDIM * DDIM) + (size_t)(by * 64) * DDIM)
                              : (g_sw1h + (size_t)(by * 64) * DDIM);
    const __half* B3 = g_w3h + (size_t)eid * (IDIM * DDIM) + (size_t)(by * 64) * DDIM;

    int tid = threadIdx.x;
    if (tid < 128) {
        int r = routed ? min(tid, rowCnt - 1) : tid;
        s_rows[tid] = routed ? g_perm[rowStart + r] : (rowStart + r);
    }
    __syncthreads();

    uint32_t dynB = smem_u32(dyns);

    auto load_stage = [&](int c) {
        if (c < NC) {
            int kk = c * 64;
            uint32_t sb = dynB + (uint32_t)((c & 1) * STG_UP);
#pragma unroll
            for (int i = 0; i < 8; i++) {
                int g = i * 256 + tid;        // 0..2047
                int row = g >> 3;             // 0..255: A 0..127, B1 128..191, B3 192..255
                int seg = (g & 7) * 8;        // halves
                if (row >= 192 && !routed) continue;
                uint32_t dst = sb + (uint32_t)(row * (SROW * 2) + seg * 2);
                const __half* src;
                if (row < 128)      src = g_xh + (size_t)s_rows[row] * DDIM + kk + seg;
                else if (row < 192) src = B1 + (size_t)(row - 128) * DDIM + kk + seg;
                else                src = B3 + (size_t)(row - 192) * DDIM + kk + seg;
                CP16(dst, src);
            }
        }
        CP_COMMIT();
    };

    int wid = tid >> 5, lane = tid & 31;
    int wm = (wid & 3) * 32;
    int wn = (wid >> 2) * 32;
    int aRow = (lane & 7) + ((lane >> 3) & 1) * 8;
    int aCol = (lane >> 4) * 8;
    int bRow = (lane & 7) + ((lane >> 4) & 1) * 8;
    int bCol = ((lane >> 3) & 1) * 8;

    float acc1[2][4][4], acc3[2][4][4];
#pragma unroll
    for (int mf = 0; mf < 2; mf++)
#pragma unroll
        for (int nf = 0; nf < 4; nf++)
#pragma unroll
            for (int r = 0; r < 4; r++) { acc1[mf][nf][r] = 0.f; acc3[mf][nf][r] = 0.f; }

    load_stage(0);

    for (int c = 0; c < NC; ++c) {
        load_stage(c + 1);
        CP_WAIT1();
        __syncthreads();
        uint32_t sbA = dynB + (uint32_t)((c & 1) * STG_UP);
        uint32_t sbB1 = sbA + 128 * (SROW * 2);
        uint32_t sbB3 = sbA + 192 * (SROW * 2);
#pragma unroll
        for (int kb = 0; kb < 64; kb += 16) {
            uint32_t ah[2][4], bh1[4][2], bh3[4][2];
#pragma unroll
            for (int mf = 0; mf < 2; mf++) {
                uint32_t off = (uint32_t)(((wm + mf * 16 + aRow) * SROW + kb + aCol) * 2);
                LDSM4(ah[mf][0], ah[mf][1], ah[mf][2], ah[mf][3], sbA + off);
            }
#pragma unroll
            for (int n2 = 0; n2 < 2; n2++) {
                uint32_t off = (uint32_t)(((wn + n2 * 16 + bRow) * SROW + kb + bCol) * 2);
                uint32_t r0, r1, r2, r3;
                LDSM4(r0, r1, r2, r3, sbB1 + off);
                bh1[n2 * 2][0] = r0; bh1[n2 * 2][1] = r1;
                bh1[n2 * 2 + 1][0] = r2; bh1[n2 * 2 + 1][1] = r3;
            }
#pragma unroll
            for (int mf = 0; mf < 2; mf++)
#pragma unroll
                for (int nf = 0; nf < 4; nf++)
                    MMAH(acc1[mf][nf], ah[mf], bh1[nf]);
            if (routed) {
#pragma unroll
                for (int n2 = 0; n2 < 2; n2++) {
                    uint32_t off = (uint32_t)(((wn + n2 * 16 + bRow) * SROW + kb + bCol) * 2);
                    uint32_t r0, r1, r2, r3;
                    LDSM4(r0, r1, r2, r3, sbB3 + off);
                    bh3[n2 * 2][0] = r0; bh3[n2 * 2][1] = r1;
                    bh3[n2 * 2 + 1][0] = r2; bh3[n2 * 2 + 1][1] = r3;
                }
#pragma unroll
                for (int mf = 0; mf < 2; mf++)
#pragma unroll
                    for (int nf = 0; nf < 4; nf++)
                        MMAH(acc3[mf][nf], ah[mf], bh3[nf]);
            }
        }
        __syncthreads();
    }

    // epilogue
#pragma unroll
    for (int mf = 0; mf < 2; mf++) {
#pragma unroll
        for (int half = 0; half < 2; half++) {
            int mloc = wm + mf * 16 + (lane >> 2) + half * 8;
            if (routed && mloc >= rowCnt) continue;
            int sp = rowStart + mloc;
#pragma unroll
            for (int nf = 0; nf < 4; nf++) {
                float v0 = acc1[mf][nf][half * 2 + 0];
                float v1 = acc1[mf][nf][half * 2 + 1];
                int colg = by * 64 + wn + nf * 8 + (lane & 3) * 2;
                size_t o = (size_t)sp * IDIM + colg;
                if (!routed) {
                    *reinterpret_cast<__half2*>(g_Hsh + o) =
                        __floats2half2_rn(gelu_exact(v0), gelu_exact(v1));
                } else {
                    float u0 = acc3[mf][nf][half * 2 + 0];
                    float u1 = acc3[mf][nf][half * 2 + 1];
                    *reinterpret_cast<__half2*>(g_Hrh + o) =
                        __floats2half2_rn(silu_f(v0) * u0, silu_f(v1) * u1);
                }
            }
        }
    }
}

// ===================== DOWN: fused shared-down + routed-down, k-chunk 64 =====================
// grid (72, 4), 256 thr. bx<32: out += Hsh @ sw2^T.  bx>=32: out[perm] += Hrh @ w2[e]^T.
__global__ __launch_bounds__(256, 2)
void down_kernel(float* __restrict__ out)
{
    constexpr int NC = IDIM / 64;   // 32
    extern __shared__ __align__(16) char dyns[];
    __shared__ int s_rows[128];

    int bx = blockIdx.x, by = blockIdx.y;
    bool routed = (bx >= 32);
    int rowStart, rowCnt; int eid = 0;
    if (routed) {
        int bt = bx - 32;
        if (bt >= g_numTiles) return;
        eid = g_tileE[bt]; rowStart = g_tileRow[bt]; rowCnt = g_tileCnt[bt];
    } else {
        rowStart = bx * 128; rowCnt = 128;
    }

    const __half* Asrc = routed ? g_Hrh : g_Hsh;
    const __half* Bsrc = routed ? (g_w2h + (size_t)eid * (DDIM * IDIM) + (size_t)(by * 128) * IDIM)
                                : (g_sw2h + (size_t)(by * 128) * IDIM);

    int tid = threadIdx.x;
    if (tid < 128) {
        int r = routed ? min(tid, rowCnt - 1) : tid;
        s_rows[tid] = rowStart + r;
    }
    __syncthreads();

    uint32_t dynB = smem_u32(dyns);

    auto load_stage = [&](int c) {
        if (c < NC) {
            int kk = c * 64;
            uint32_t sb = dynB + (uint32_t)((c & 1) * STG_DN);
#pragma unroll
            for (int i = 0; i < 8; i++) {
                int g = i * 256 + tid;
                int row2 = g >> 3;            // 0..255
                int seg = (g & 7) * 8;
                int isB = (row2 >= 128);
                int row = row2 & 127;
                uint32_t dst = sb + (uint32_t)(row2 * (SROW * 2) + seg * 2);
                const __half* src = isB ? (Bsrc + (size_t)row * IDIM + kk + seg)
                                        : (Asrc + (size_t)s_rows[row] * IDIM + kk + seg);
                CP16(dst, src);
            }
        }
        CP_COMMIT();
    };

    int wid = tid >> 5, lane = tid & 31;
    int wm = (wid & 3) * 32;
    int wn = (wid >> 2) * 64;
    int aRow = (lane & 7) + ((lane >> 3) & 1) * 8;
    int aCol = (lane >> 4) * 8;
    int bRow = (lane & 7) + ((lane >> 4) & 1) * 8;
    int bCol = ((lane >> 3) & 1) * 8;

    float acc[2][8][4];
#pragma unroll
    for (int mf = 0; mf < 2; mf++)
#pragma unroll
        for (int nf = 0; nf < 8; nf++)
#pragma unroll
            for (int r = 0; r < 4; r++) acc[mf][nf][r] = 0.f;

    load_stage(0);

    for (int c = 0; c < NC; ++c) {
        load_stage(c + 1);
        CP_WAIT1();
        __syncthreads();
        uint32_t sbA = dynB + (uint32_t)((c & 1) * STG_DN);
        uint32_t sbB = sbA + 128 * (SROW * 2);
#pragma unroll
        for (int kb = 0; kb < 64; kb += 16) {
            uint32_t ah[2][4], bh[8][2];
#pragma unroll
            for (int mf = 0; mf < 2; mf++) {
                uint32_t off = (uint32_t)(((wm + mf * 16 + aRow) * SROW + kb + aCol) * 2);
                LDSM4(ah[mf][0], ah[mf][1], ah[mf][2], ah[mf][3], sbA + off);
            }
#pragma unroll
            for (int n2 = 0; n2 < 4; n2++) {
                uint32_t off = (uint32_t)(((wn + n2 * 16 + bRow) * SROW + kb + bCol) * 2);
                uint32_t r0, r1, r2, r3;
                LDSM4(r0, r1, r2, r3, sbB + off);
                bh[n2 * 2][0] = r0; bh[n2 * 2][1] = r1;
                bh[n2 * 2 + 1][0] = r2; bh[n2 * 2 + 1][1] = r3;
            }
#pragma unroll
            for (int mf = 0; mf < 2; mf++)
#pragma unroll
                for (int nf = 0; nf < 8; nf++)
                    MMAH(acc[mf][nf], ah[mf], bh[nf]);
        }
        __syncthreads();
    }

#pragma unroll
    for (int mf = 0; mf < 2; mf++) {
#pragma unroll
        for (int half = 0; half < 2; half++) {
            int mloc = wm + mf * 16 + (lane >> 2) + half * 8;
            if (routed && mloc >= rowCnt) continue;
            int sp = rowStart + mloc;
            int tok = routed ? g_perm[sp] : sp;
            float* orow = out + (size_t)tok * DDIM;
#pragma unroll
            for (int nf = 0; nf < 8; nf++) {
                int colg = by * 128 + wn + nf * 8 + (lane & 3) * 2;
                atomicAdd(orow + colg,     acc[mf][nf][half * 2 + 0]);
                atomicAdd(orow + colg + 1, acc[mf][nf][half * 2 + 1]);
            }
        }
    }
}

// ===================== launch =====================
extern "C" void kernel_launch(void* const* d_in, const int* in_sizes, int n_in,
                              void* d_out, int out_size) {
    const float* x   = (const float*)d_in[0];   // [4096, 512]
    const float* gw  = (const float*)d_in[1];   // [8, 512]
    const float* w1  = (const float*)d_in[2];   // [8, 2048, 512]
    const float* w2  = (const float*)d_in[3];   // [8, 512, 2048]
    const float* w3  = (const float*)d_in[4];   // [8, 2048, 512]
    const float* sw1 = (const float*)d_in[5];   // [2048, 512]
    const float* sw2 = (const float*)d_in[6];   // [512, 2048]
    float* out = (float*)d_out;                 // [4096, 512]

    cudaMemsetAsync(out, 0, (size_t)out_size * sizeof(float));
    cvt_all<<<(int)((C_W2 + 255) / 256), 256>>>(x, sw1, sw2, w1, w3, w2);
    gate_kernel<<<NTOK / 8, 256>>>(x, gw);
    build_scatter_kernel<<<1, 256>>>();

    cudaFuncSetAttribute(up_kernel,   cudaFuncAttributeMaxDynamicSharedMemorySize, SM_UP);
    cudaFuncSetAttribute(down_kernel, cudaFuncAttributeMaxDynamicSharedMemorySize, SM_DN);

    up_kernel<<<dim3(72, IDIM / 64), 256, SM_UP>>>();
    down_kernel<<<dim3(72, 4), 256, SM_DN>>>(out);
}